// round 13
// baseline (speedup 1.0000x reference)
#include <cuda_runtime.h>
#include <cuda_bf16.h>
#include <cstdint>

#define BATCHN 32
#define SEQ    1024
#define DIM    128
#define KC     32
#define NITER  (SEQ / KC)
#define PK     136

// ---------------- helpers ----------------
__device__ __forceinline__ unsigned smaddr(const void* p) {
    return (unsigned)__cvta_generic_to_shared(p);
}
__device__ __forceinline__ void ldsm4(unsigned* r, unsigned a) {
    asm volatile("ldmatrix.sync.aligned.m8n8.x4.shared.b16 {%0,%1,%2,%3},[%4];"
                 : "=r"(r[0]), "=r"(r[1]), "=r"(r[2]), "=r"(r[3]) : "r"(a));
}
__device__ __forceinline__ void ldsm4t(unsigned* r, unsigned a) {
    asm volatile("ldmatrix.sync.aligned.m8n8.x4.trans.shared.b16 {%0,%1,%2,%3},[%4];"
                 : "=r"(r[0]), "=r"(r[1]), "=r"(r[2]), "=r"(r[3]) : "r"(a));
}
__device__ __forceinline__ void mma16816(float* c, const unsigned* a, const unsigned* b) {
    asm volatile("mma.sync.aligned.m16n8k16.row.col.f32.bf16.bf16.f32 "
                 "{%0,%1,%2,%3},{%4,%5,%6,%7},{%8,%9},{%0,%1,%2,%3};"
                 : "+f"(c[0]), "+f"(c[1]), "+f"(c[2]), "+f"(c[3])
                 : "r"(a[0]), "r"(a[1]), "r"(a[2]), "r"(a[3]), "r"(b[0]), "r"(b[1]));
}
__device__ __forceinline__ unsigned packbf(float lo, float hi) {
    unsigned r;
    asm("cvt.rn.bf16x2.f32 %0, %1, %2;" : "=r"(r) : "f"(hi), "f"(lo));
    return r;
}
__device__ __forceinline__ float lrelu(float x) { return x >= 0.f ? x : 0.1f * x; }
__device__ __forceinline__ float bfh(float x) {
    return __bfloat162float(__float2bfloat16_rn(x));
}
__device__ __forceinline__ uint4 pack4(float4 a, float4 b) {
    return make_uint4(packbf(a.x, a.y), packbf(a.z, a.w),
                      packbf(b.x, b.y), packbf(b.z, b.w));
}

// smem map (bytes):
//  phase1: mask 2 stages @0 (17408) + nodes 2 stages @17408 (17408) -> [0, 34816)
//  phase2: 2 chunk stages @0, each 25344 (W/Bh/Bl 16x272B, SH/SL 128x48B) -> [0, 50688)
//  P bf16 [128][PK] @50688 (34816) -> [50688, 85504)
#define OFF_NODE 17408
#define OFF_P    50688
#define STGSZ    25344
#define C_W      0
#define C_BH     4352
#define C_BL     8704
#define C_SH     13056
#define C_SL     19200
#define CH       16
#define NCH      8
#define SMEM_SZ  85504

__global__ __launch_bounds__(256, 2)
void gcn_fused_kernel(const float* __restrict__ nodes, const int* __restrict__ adj,
                      const float* __restrict__ Wm, const float* __restrict__ Bm,
                      float* __restrict__ out)
{
    extern __shared__ __align__(16) unsigned char smem[];
    __shared__ int scnt[128];

    const int t    = threadIdx.x;
    const int lane = t & 31;
    const int wid  = t >> 5;
    const int wm   = wid >> 1;     // 0..3 : owns 32 i-rows
    const int wn   = wid & 1;      // 0..1 : owns 64 d-cols
    const int b    = blockIdx.y;
    const int i0   = blockIdx.x * 128;

    if (t < 128) scnt[t] = 0;

    const int*   adjBase = adj   + (long long)b * SEQ * SEQ + i0 + 4 * lane;
    const float* nodesB  = nodes + (long long)b * SEQ * DIM;

    // phase-1 node staging coords: chunk0 row = t>>4 (0..15), chunk1 row +16; col = (t&15)*8
    const int ncRow = t >> 4, ncCol = t & 15;
    const float* nsrc0 = nodesB + ncRow * DIM + ncCol * 8;   // + it*KC*DIM; chunk1 at +16*DIM

    // ---- prefetch iter 0 ----
    int4 mreg[4];
#pragma unroll
    for (int p = 0; p < 4; p++)
        mreg[p] = *(const int4*)(adjBase + (long long)(wid + 8 * p) * SEQ);
    uint4 npk0, npk1;
    {
        float4 a0 = *(const float4*)(nsrc0);
        float4 a1 = *(const float4*)(nsrc0 + 4);
        float4 b0 = *(const float4*)(nsrc0 + 16 * DIM);
        float4 b1 = *(const float4*)(nsrc0 + 16 * DIM + 4);
        npk0 = pack4(a0, a1);
        npk1 = pack4(b0, b1);
    }

    float c[64];
#pragma unroll
    for (int i = 0; i < 64; i++) c[i] = 0.f;
    int cnt0 = 0, cnt1 = 0, cnt2 = 0, cnt3 = 0;

    // ldmatrix offsets
    const unsigned aRow  = (lane & 7) + ((lane >> 4) & 1) * 8;
    const unsigned aCol8 = ((lane >> 3) & 1) * 8;
    const unsigned bRow  = (lane & 7) + ((lane >> 3) & 1) * 8;
    const unsigned bCol8 = ((lane >> 4) & 1) * 8;
    const unsigned bOff  = (bRow * PK + bCol8) * 2;
    const unsigned maskSm = smaddr(smem);
    const unsigned nodeSm = smaddr(smem + OFF_NODE);

    for (int it = 0; it < NITER; ++it) {
        // ---- produce stage (it&1): nodes (from converted regs) + mask (+counts) ----
        {
            unsigned char* nst = smem + OFF_NODE + (it & 1) * 8704;
            *(uint4*)(nst + ncRow * 272 + ncCol * 16)        = npk0;
            *(uint4*)(nst + (16 + ncRow) * 272 + ncCol * 16) = npk1;
        }
        unsigned mst = (it & 1) * 8704;
#pragma unroll
        for (int p = 0; p < 4; p++) {
            int o = wid + 8 * p;
            int4 m = mreg[p];
            cnt0 += (m.x != 0); cnt1 += (m.y != 0); cnt2 += (m.z != 0); cnt3 += (m.w != 0);
            unsigned lo = (m.x ? 0x3F80u : 0u) | (m.y ? 0x3F800000u : 0u);
            unsigned hi = (m.z ? 0x3F80u : 0u) | (m.w ? 0x3F800000u : 0u);
            *(uint2*)(smem + mst + (o * PK + 4 * lane) * 2) = make_uint2(lo, hi);
        }
        // ---- prefetch it+1 (overlaps MMA below) ----
        if (it + 1 < NITER) {
            const int* ab = adjBase + (long long)(it + 1) * KC * SEQ;
#pragma unroll
            for (int p = 0; p < 4; p++)
                mreg[p] = *(const int4*)(ab + (long long)(wid + 8 * p) * SEQ);
            const float* ns = nsrc0 + (it + 1) * KC * DIM;
            float4 a0 = *(const float4*)(ns);
            float4 a1 = *(const float4*)(ns + 4);
            float4 b0 = *(const float4*)(ns + 16 * DIM);
            float4 b1 = *(const float4*)(ns + 16 * DIM + 4);
            npk0 = pack4(a0, a1);
            npk1 = pack4(b0, b1);
        }
        __syncthreads();

        // ---- consume stage (it&1): 2D warp tile 32i x 64d ----
        const unsigned mA = maskSm + (it & 1) * 8704;
        const unsigned nB = nodeSm + (it & 1) * 8704;
#pragma unroll
        for (int kk = 0; kk < 2; kk++) {
            unsigned a0[4], a1[4];
            ldsm4t(a0, mA + ((kk * 16 + aRow) * PK + wm * 32 + aCol8) * 2);
            ldsm4t(a1, mA + ((kk * 16 + aRow) * PK + wm * 32 + 16 + aCol8) * 2);
#pragma unroll
            for (int ng = 0; ng < 4; ng++) {
                unsigned bb[4];
                ldsm4t(bb, nB + ((kk * 16 + bRow) * PK + wn * 64 + ng * 16 + bCol8) * 2);
                mma16816(c + (2 * ng + 0) * 4,     a0, bb);
                mma16816(c + (2 * ng + 1) * 4,     a0, bb + 2);
                mma16816(c + (8 + 2 * ng + 0) * 4, a1, bb);
                mma16816(c + (8 + 2 * ng + 1) * 4, a1, bb + 2);
            }
        }
    }

    atomicAdd(&scnt[4 * lane + 0], cnt0);
    atomicAdd(&scnt[4 * lane + 1], cnt1);
    atomicAdd(&scnt[4 * lane + 2], cnt2);
    atomicAdd(&scnt[4 * lane + 3], cnt3);
    __syncthreads();   // scnt valid; phase-1 smem dead

    // ================= phase 2 =================
    // staging macros: chunk = 16 d-rows; stage (jc&1)
    const float* selfF = nodes + ((long long)b * SEQ + i0 + (t >> 1)) * DIM + (t & 1) * 8;
    const float* wSrc  = Wm + ncRow * DIM + ncCol * 8;   // + jc*CH*DIM
    const float* bSrc  = Bm + ncRow * DIM + ncCol * 8;

#define STAGE_WB(JC, WA, WB, BA, BB) do {                                         \
        unsigned char* _p = smem + ((JC) & 1) * STGSZ;                            \
        unsigned _so = ncRow * 272 + ncCol * 16;                                  \
        *(uint4*)(_p + C_W + _so) = pack4(WA, WB);                                \
        float _h0 = bfh((BA).x), _h1 = bfh((BA).y), _h2 = bfh((BA).z), _h3 = bfh((BA).w); \
        float _h4 = bfh((BB).x), _h5 = bfh((BB).y), _h6 = bfh((BB).z), _h7 = bfh((BB).w); \
        *(uint4*)(_p + C_BH + _so) = make_uint4(packbf(_h0, _h1), packbf(_h2, _h3), \
                                                packbf(_h4, _h5), packbf(_h6, _h7)); \
        *(uint4*)(_p + C_BL + _so) =                                              \
            make_uint4(packbf((BA).x - _h0, (BA).y - _h1),                        \
                       packbf((BA).z - _h2, (BA).w - _h3),                        \
                       packbf((BB).x - _h4, (BB).y - _h5),                        \
                       packbf((BB).z - _h6, (BB).w - _h7));                       \
    } while (0)

#define STS_SELF(JC, VA, VB) do {                                                 \
        unsigned char* _p = smem + ((JC) & 1) * STGSZ;                            \
        float _h0 = bfh((VA).x), _h1 = bfh((VA).y), _h2 = bfh((VA).z), _h3 = bfh((VA).w); \
        float _h4 = bfh((VB).x), _h5 = bfh((VB).y), _h6 = bfh((VB).z), _h7 = bfh((VB).w); \
        *(uint4*)(_p + C_SH + (t >> 1) * 48 + (t & 1) * 16) =                     \
            make_uint4(packbf(_h0, _h1), packbf(_h2, _h3),                        \
                       packbf(_h4, _h5), packbf(_h6, _h7));                       \
        *(uint4*)(_p + C_SL + (t >> 1) * 48 + (t & 1) * 16) =                     \
            make_uint4(packbf((VA).x - _h0, (VA).y - _h1),                        \
                       packbf((VA).z - _h2, (VA).w - _h3),                        \
                       packbf((VB).x - _h4, (VB).y - _h5),                        \
                       packbf((VB).z - _h6, (VB).w - _h7));                       \
    } while (0)

#define LOAD_CHUNK(JC, SA, SB, WA, WB, BA, BB) do {                               \
        SA = *(const float4*)(selfF + (JC) * CH);                                 \
        SB = *(const float4*)(selfF + (JC) * CH + 4);                             \
        WA = *(const float4*)(wSrc + (JC) * CH * DIM);                            \
        WB = *(const float4*)(wSrc + (JC) * CH * DIM + 4);                        \
        BA = *(const float4*)(bSrc + (JC) * CH * DIM);                            \
        BB = *(const float4*)(bSrc + (JC) * CH * DIM + 4);                        \
    } while (0)

    // prologue: stage chunks 0,1 while normalizing P
    float4 sA, sB, wA, wB, bA, bB;
    LOAD_CHUNK(0, sA, sB, wA, wB, bA, bB);

    // normalize P (2D fragment layout) and store bf16 to P region
    {
        const int rBase = wm * 32 + (lane >> 2);
        const float i00 = 1.f / fmaxf((float)scnt[rBase], 1.f);
        const float i01 = 1.f / fmaxf((float)scnt[rBase + 8], 1.f);
        const float i10 = 1.f / fmaxf((float)scnt[rBase + 16], 1.f);
        const float i11 = 1.f / fmaxf((float)scnt[rBase + 24], 1.f);
        unsigned char* P = smem + OFF_P;
        const int colB = wn * 64 + 2 * (lane & 3);
#pragma unroll
        for (int mt = 0; mt < 2; mt++) {
            const float ivA = mt ? i10 : i00;
            const float ivB = mt ? i11 : i01;
            const int r0 = rBase + mt * 16;
#pragma unroll
            for (int nn = 0; nn < 8; nn++) {
                float* cc = c + (mt * 8 + nn) * 4;
                const int col = colB + nn * 8;
                *(unsigned*)(P + (r0 * PK + col) * 2)       = packbf(cc[0] * ivA, cc[1] * ivA);
                *(unsigned*)(P + ((r0 + 8) * PK + col) * 2) = packbf(cc[2] * ivB, cc[3] * ivB);
            }
        }
    }
    STAGE_WB(0, wA, wB, bA, bB);
    STS_SELF(0, sA, sB);
    LOAD_CHUNK(1, sA, sB, wA, wB, bA, bB);
    STAGE_WB(1, wA, wB, bA, bB);
    STS_SELF(1, sA, sB);

#pragma unroll
    for (int i = 0; i < 64; i++) c[i] = 0.f;

    const unsigned aS2     = ((wid * 16 + (lane & 15)) * 24 + ((lane >> 4) & 1) * 8) * 2;
    const unsigned aP_base = ((wid * 16 + (lane & 15)) * PK + ((lane >> 4) & 1) * 8) * 2;
    const unsigned Psm = maskSm + OFF_P;

#pragma unroll 1
    for (int jc = 0; jc < NCH; ++jc) {
        __syncthreads();   // chunk jc staged & visible

        if (jc + 2 < NCH) LOAD_CHUNK(jc + 2, sA, sB, wA, wB, bA, bB);

        const unsigned st = maskSm + (jc & 1) * STGSZ;
        unsigned aH[4], aL[4], aP[4];
        ldsm4(aH, st + C_SH + aS2);
        ldsm4(aL, st + C_SL + aS2);
        ldsm4(aP, Psm + aP_base + jc * CH * 2);
#pragma unroll
        for (int nb = 0; nb < 8; nb++) {
            const unsigned off = bOff + nb * 16 * 2;
            unsigned bW[4], bH[4], bL[4];
            ldsm4t(bW, st + C_W  + off);
            ldsm4t(bH, st + C_BH + off);
            ldsm4t(bL, st + C_BL + off);
            float* cc0 = c + 8 * nb;
            float* cc1 = c + 8 * nb + 4;
            mma16816(cc0, aP, bW);  mma16816(cc1, aP, bW + 2);
            mma16816(cc0, aH, bH);  mma16816(cc1, aH, bH + 2);
            mma16816(cc0, aH, bL);  mma16816(cc1, aH, bL + 2);
            mma16816(cc0, aL, bH);  mma16816(cc1, aL, bH + 2);
        }
        __syncthreads();   // all consumers done with stage (jc&1)
        if (jc + 2 < NCH) {
            STAGE_WB(jc + 2, wA, wB, bA, bB);
            STS_SELF(jc + 2, sA, sB);
        }
    }

    const int orow = i0 + wid * 16 + (lane >> 2);
    const int ocol = 2 * (lane & 3);
    float* outB = out + ((long long)b * SEQ + orow) * DIM;
#pragma unroll
    for (int nt = 0; nt < 16; nt++) {
        int colx = 8 * nt + ocol;
        float2 v01 = make_float2(lrelu(c[4 * nt + 0]), lrelu(c[4 * nt + 1]));
        float2 v23 = make_float2(lrelu(c[4 * nt + 2]), lrelu(c[4 * nt + 3]));
        *(float2*)(outB + colx)           = v01;
        *(float2*)(outB + 8 * DIM + colx) = v23;
    }
}

extern "C" void kernel_launch(void* const* d_in, const int* in_sizes, int n_in,
                              void* d_out, int out_size)
{
    (void)in_sizes; (void)n_in; (void)out_size;
    const float* nodes = (const float*)d_in[0];
    const int*   adj   = (const int*)d_in[1];
    const float* Wm    = (const float*)d_in[2];
    const float* Bm    = (const float*)d_in[3];
    float*       out   = (float*)d_out;

    cudaFuncSetAttribute(gcn_fused_kernel,
                         cudaFuncAttributeMaxDynamicSharedMemorySize, SMEM_SZ);

    dim3 grid(SEQ / 128, BATCHN);
    gcn_fused_kernel<<<grid, 256, SMEM_SZ>>>(nodes, adj, Wm, Bm, out);
}